// round 11
// baseline (speedup 1.0000x reference)
#include <cuda_runtime.h>
#include <cuda_bf16.h>
#include <stdint.h>
#include <math.h>

// Problem constants
constexpr int N_  = 4;
constexpr int P_  = 2048;
constexpr int D_  = 512;
constexpr int H_  = 8;
constexpr int HD_ = 64;
constexpr int NH_ = N_ * H_;                              // 32
constexpr long long NPD_  = (long long)N_ * P_ * D_;      // 4194304
constexpr long long NHPP_ = (long long)N_ * H_ * P_ * P_; // 134217728
constexpr float SCALE_ = 0.044194173824159216f;           // 1/sqrt(512)

// ---------------------------------------------------------------------------
// Scratch (device globals; allocation-free per harness rules)
// ---------------------------------------------------------------------------
__device__ __align__(16) __nv_bfloat16 g_qh[NH_ * P_ * HD_];
__device__ __align__(16) __nv_bfloat16 g_ql[NH_ * P_ * HD_];
__device__ __align__(16) __nv_bfloat16 g_kh[NH_ * P_ * HD_];
__device__ __align__(16) __nv_bfloat16 g_kl[NH_ * P_ * HD_];
__device__ __align__(16) __nv_bfloat16 g_vth[NH_ * HD_ * P_]; // V^T [nh][e][p]
__device__ __align__(16) __nv_bfloat16 g_vtl[NH_ * HD_ * P_];
__device__ __align__(16) __nv_bfloat16 g_uh[NHPP_];  // u = exp(S - m_tile) hi
__device__ __align__(16) __nv_bfloat16 g_ul[NHPP_];  // u lo
__device__ __align__(16) __nv_bfloat16 g_oh[NPD_];   // O flat [n][p][512] hi
__device__ __align__(16) __nv_bfloat16 g_ol[NPD_];
__device__ __align__(16) __nv_bfloat16 g_woh[D_ * D_];
__device__ __align__(16) __nv_bfloat16 g_wol[D_ * D_];
__device__ float g_pm[NH_ * 16 * P_];     // per-ktile row max partial
__device__ float g_ps[NH_ * 16 * P_];     // per-ktile row sumexp partial
__device__ float g_attn[NHPP_];           // fallback if attention not in d_out

// ---------------------------------------------------------------------------
// Helpers
// ---------------------------------------------------------------------------
__device__ __forceinline__ uint32_t smem_u32(const void* p) {
    uint32_t a;
    asm("{ .reg .u64 t; cvta.to.shared.u64 t, %1; cvt.u32.u64 %0, t; }"
        : "=r"(a) : "l"(p));
    return a;
}

__device__ __forceinline__ void ldsm4(uint32_t* r, uint32_t a) {
    asm volatile("ldmatrix.sync.aligned.m8n8.x4.shared.b16 {%0,%1,%2,%3}, [%4];"
                 : "=r"(r[0]), "=r"(r[1]), "=r"(r[2]), "=r"(r[3]) : "r"(a));
}

__device__ __forceinline__ void mma16816(float* d, const uint32_t* a,
                                         uint32_t b0, uint32_t b1) {
    asm volatile("mma.sync.aligned.m16n8k16.row.col.f32.bf16.bf16.f32 "
                 "{%0,%1,%2,%3},{%4,%5,%6,%7},{%8,%9},{%0,%1,%2,%3};"
                 : "+f"(d[0]), "+f"(d[1]), "+f"(d[2]), "+f"(d[3])
                 : "r"(a[0]), "r"(a[1]), "r"(a[2]), "r"(a[3]), "r"(b0), "r"(b1));
}

__device__ __forceinline__ void cpa16(uint32_t d, const void* s) {
    asm volatile("cp.async.cg.shared.global [%0], [%1], 16;" :: "r"(d), "l"(s));
}
#define CP_COMMIT() asm volatile("cp.async.commit_group;" ::: "memory")
#define CP_WAIT1()  asm volatile("cp.async.wait_group 1;" ::: "memory")
#define CP_WAIT0()  asm volatile("cp.async.wait_group 0;" ::: "memory")

// Fast exp on the FFMA pipe (valid for x <= 0; ~1e-7 rel err). Avoids MUFU.
__device__ __forceinline__ float fexp(float x) {
    float t = x * 1.4426950408889634f;
    t = fmaxf(t, -120.f);
    float z = t + 12582912.f;
    int   n = __float_as_int(z) - 0x4B400000;
    float f = t - (z - 12582912.f);
    float r = 1.5403530393381609e-4f;
    r = fmaf(r, f, 1.3333558146428443e-3f);
    r = fmaf(r, f, 9.6181291076284772e-3f);
    r = fmaf(r, f, 5.5504108664821580e-2f);
    r = fmaf(r, f, 2.4022650695910072e-1f);
    r = fmaf(r, f, 6.9314718055994531e-1f);
    r = fmaf(r, f, 1.0f);
    return __int_as_float(__float_as_int(r) + (n << 23));
}

__device__ __forceinline__ unsigned short bfu(__nv_bfloat16 b) {
    return __bfloat16_as_ushort(b);
}
__device__ __forceinline__ uint32_t packbf(float a, float b) {
    return (uint32_t)bfu(__float2bfloat16(a)) |
           ((uint32_t)bfu(__float2bfloat16(b)) << 16);
}
__device__ __forceinline__ float2 bf2f(uint32_t w) {
    __nv_bfloat162 b = *reinterpret_cast<__nv_bfloat162*>(&w);
    return make_float2(__bfloat162float(b.x), __bfloat162float(b.y));
}

// ---------------------------------------------------------------------------
// K0: split Wo into bf16 hi/lo
// ---------------------------------------------------------------------------
__global__ __launch_bounds__(256) void wo_split_kernel(const float* __restrict__ Wo)
{
    int i = blockIdx.x * 256 + threadIdx.x;
    if (i < D_ * D_) {
        float v = Wo[i];
        __nv_bfloat16 hb = __float2bfloat16(v);
        g_woh[i] = hb;
        g_wol[i] = __float2bfloat16(v - __bfloat162float(hb));
    }
}

// ---------------------------------------------------------------------------
// K1: QKV projection (fp32 FFMA) -> bf16 hi/lo outputs.
// ---------------------------------------------------------------------------
__global__ __launch_bounds__(256) void qkv_kernel(
    const float* __restrict__ xyz,
    const float* __restrict__ Wq,
    const float* __restrict__ Wk,
    const float* __restrict__ Wv)
{
    __shared__ float xs[64][65];
    __shared__ float Wt[64][68];

    int ptile = blockIdx.x, nh = blockIdx.y;
    int n = nh / H_, h = nh % H_;
    int p0 = ptile * 64;
    int tid = threadIdx.x;

    for (int i = tid; i < 4096; i += 256) {
        int row = i >> 6, dd = i & 63;
        xs[row][dd] = xyz[(n * P_ + p0 + row) * D_ + h * HD_ + dd];
    }

    int tx = tid & 15, ty = tid >> 4;
    int r = ty * 4, c = tx * 4;
    const float* Ws[3] = {Wq, Wk, Wv};

    for (int m = 0; m < 3; ++m) {
        __syncthreads();
        const float* W = Ws[m];
        for (int i = tid; i < 4096; i += 256) {
            int e = i >> 6, dd = i & 63;
            Wt[dd][e] = W[i];
        }
        __syncthreads();

        float acc[4][4] = {};
        #pragma unroll
        for (int dd = 0; dd < 64; ++dd) {
            float a0 = xs[r + 0][dd], a1 = xs[r + 1][dd];
            float a2 = xs[r + 2][dd], a3 = xs[r + 3][dd];
            float4 b = *(const float4*)&Wt[dd][c];
            acc[0][0] += a0 * b.x; acc[0][1] += a0 * b.y; acc[0][2] += a0 * b.z; acc[0][3] += a0 * b.w;
            acc[1][0] += a1 * b.x; acc[1][1] += a1 * b.y; acc[1][2] += a1 * b.z; acc[1][3] += a1 * b.w;
            acc[2][0] += a2 * b.x; acc[2][1] += a2 * b.y; acc[2][2] += a2 * b.z; acc[2][3] += a2 * b.w;
            acc[3][0] += a3 * b.x; acc[3][1] += a3 * b.y; acc[3][2] += a3 * b.z; acc[3][3] += a3 * b.w;
        }

        if (m < 2) {
            float sc = (m == 0) ? SCALE_ : 1.0f;
            __nv_bfloat16* Ah = (m == 0) ? g_qh : g_kh;
            __nv_bfloat16* Al = (m == 0) ? g_ql : g_kl;
            #pragma unroll
            for (int i = 0; i < 4; ++i) {
                long long idx = ((long long)(nh * P_ + p0 + r + i)) * 64 + c;
                float v0 = acc[i][0] * sc, v1 = acc[i][1] * sc;
                float v2 = acc[i][2] * sc, v3 = acc[i][3] * sc;
                __nv_bfloat16 h0 = __float2bfloat16(v0), h1 = __float2bfloat16(v1);
                __nv_bfloat16 h2 = __float2bfloat16(v2), h3 = __float2bfloat16(v3);
                *(ushort4*)&Ah[idx] = make_ushort4(bfu(h0), bfu(h1), bfu(h2), bfu(h3));
                *(ushort4*)&Al[idx] = make_ushort4(
                    bfu(__float2bfloat16(v0 - __bfloat162float(h0))),
                    bfu(__float2bfloat16(v1 - __bfloat162float(h1))),
                    bfu(__float2bfloat16(v2 - __bfloat162float(h2))),
                    bfu(__float2bfloat16(v3 - __bfloat162float(h3))));
            }
        } else {
            __syncthreads();
            #pragma unroll
            for (int i = 0; i < 4; ++i)
                #pragma unroll
                for (int j = 0; j < 4; ++j)
                    xs[c + j][r + i] = acc[i][j];
            __syncthreads();
            for (int i = tid; i < 4096; i += 256) {
                int e = i >> 6, pp = i & 63;
                float v = xs[e][pp];
                __nv_bfloat16 hb = __float2bfloat16(v);
                long long idx = (long long)(nh * 64 + e) * P_ + p0 + pp;
                g_vth[idx] = hb;
                g_vtl[idx] = __float2bfloat16(v - __bfloat162float(hb));
            }
        }
    }
}

// ---------------------------------------------------------------------------
// K2: S = QK^T via mma.sync bf16 hi/lo (3 passes). 512 threads, 16 warps.
//   Warp tile: 16 rows x 64 cols (wm = wid>>1, wn = wid&1).
//   Epilogue: per-tile row stats -> g_pm/g_ps; u = exp(S - m_tile) bf16 hi/lo
//   streamed to g_uh/g_ul.
// smem (dynamic 73728): QH 0 / QL 18432 / KH 36864 / KL 55296 (stride 144B).
//   Reused: UHS 0, ULS 34816 (stride 272B); Mrow 69632; wmax 70144; wsum 71168.
// ---------------------------------------------------------------------------
constexpr int TSB = 144;

__global__ __launch_bounds__(512) void scores_tc()
{
    extern __shared__ char sm[];
    uint32_t sb = smem_u32(sm);
    int tid = threadIdx.x, lane = tid & 31, wid = tid >> 5;
    int kt = blockIdx.x, qt = blockIdx.y, nh = blockIdx.z;
    int q0 = qt * 128, k0 = kt * 128;

    const int QH = 0, QL = 18432, KH = 36864, KL = 55296;
    {
        const __nv_bfloat16* srcs[4] = {
            g_qh + (long long)(nh * P_ + q0) * 64,
            g_ql + (long long)(nh * P_ + q0) * 64,
            g_kh + (long long)(nh * P_ + k0) * 64,
            g_kl + (long long)(nh * P_ + k0) * 64};
        const int offs[4] = {QH, QL, KH, KL};
        #pragma unroll
        for (int t = 0; t < 4; ++t) {
            #pragma unroll
            for (int i = 0; i < 2; ++i) {
                int lin = i * 512 + tid;
                int row = lin >> 3, c8 = lin & 7;
                *(uint4*)(sm + offs[t] + row * TSB + c8 * 16) =
                    *(const uint4*)(srcs[t] + row * 64 + c8 * 8);
            }
        }
    }
    __syncthreads();

    int wm = wid >> 1, wn = wid & 1;   // 8 row-groups x 2 col-halves
    float acc[8][4] = {};
    uint32_t aoff = (uint32_t)(wm * 16 + (lane & 15)) * TSB + ((lane & 16) ? 16u : 0u);
    uint32_t boff = (uint32_t)(wn * 64 + (lane & 7) + ((lane & 16) ? 8 : 0)) * TSB +
                    ((lane & 8) ? 16u : 0u);

    #pragma unroll
    for (int pass = 0; pass < 3; ++pass) {
        uint32_t Ab = sb + (pass == 2 ? QL : QH);
        uint32_t Bb = sb + (pass == 1 ? KL : KH);
        #pragma unroll
        for (int ks = 0; ks < 4; ++ks) {
            uint32_t af[4], bf2[4][4];
            ldsm4(af, Ab + aoff + ks * 32);
            #pragma unroll
            for (int np = 0; np < 4; ++np)
                ldsm4(bf2[np], Bb + boff + np * 16 * TSB + ks * 32);
            #pragma unroll
            for (int ni = 0; ni < 8; ++ni)
                mma16816(acc[ni], af,
                         bf2[ni >> 1][(ni & 1) * 2], bf2[ni >> 1][(ni & 1) * 2 + 1]);
        }
    }
    __syncthreads();   // operands fully consumed before smem reuse

    float* Mrow = (float*)(sm + 69632);
    float* wmax = (float*)(sm + 70144);
    float* wsum = (float*)(sm + 71168);
    int g = lane >> 2, tg = lane & 3;

    #pragma unroll
    for (int h = 0; h < 2; ++h) {
        float m = -1e30f;
        #pragma unroll
        for (int ni = 0; ni < 8; ++ni)
            m = fmaxf(m, fmaxf(acc[ni][h * 2], acc[ni][h * 2 + 1]));
        m = fmaxf(m, __shfl_xor_sync(0xFFFFFFFFu, m, 1));
        m = fmaxf(m, __shfl_xor_sync(0xFFFFFFFFu, m, 2));
        if (tg == 0) wmax[(wm * 16 + h * 8 + g) * 2 + wn] = m;
    }
    __syncthreads();
    if (tid < 128) {
        float M = fmaxf(wmax[tid * 2], wmax[tid * 2 + 1]);
        Mrow[tid] = M;
        g_pm[(nh * 16 + kt) * P_ + q0 + tid] = M;
    }
    __syncthreads();

    // exp + split + stage (uint32 packed bf16 pairs)
    #pragma unroll
    for (int h = 0; h < 2; ++h) {
        int row = wm * 16 + h * 8 + g;
        float M = Mrow[row];
        float s = 0.f;
        #pragma unroll
        for (int ni = 0; ni < 8; ++ni) {
            float u0 = fexp(acc[ni][h * 2] - M);
            float u1 = fexp(acc[ni][h * 2 + 1] - M);
            s += u0 + u1;
            int col = wn * 64 + ni * 8 + tg * 2;
            __nv_bfloat16 h0 = __float2bfloat16(u0);
            __nv_bfloat16 h1 = __float2bfloat16(u1);
            uint32_t ph = (uint32_t)bfu(h0) | ((uint32_t)bfu(h1) << 16);
            uint32_t pl = packbf(u0 - __bfloat162float(h0),
                                 u1 - __bfloat162float(h1));
            *(uint32_t*)(sm + 0     + row * 272 + col * 2) = ph;
            *(uint32_t*)(sm + 34816 + row * 272 + col * 2) = pl;
        }
        s += __shfl_xor_sync(0xFFFFFFFFu, s, 1);
        s += __shfl_xor_sync(0xFFFFFFFFu, s, 2);
        if (tg == 0) wsum[row * 2 + wn] = s;
    }
    __syncthreads();
    if (tid < 128)
        g_ps[(nh * 16 + kt) * P_ + q0 + tid] = wsum[tid * 2] + wsum[tid * 2 + 1];

    long long ub = ((long long)nh << 22) + (long long)q0 * 2048 + k0;
    #pragma unroll
    for (int i = 0; i < 4; ++i) {
        int lin = i * 512 + tid;
        int row = lin >> 4, c16 = lin & 15;
        *(uint4*)(g_uh + ub + (long long)row * 2048 + c16 * 8) =
            *(uint4*)(sm + 0 + row * 272 + c16 * 16);
        *(uint4*)(g_ul + ub + (long long)row * 2048 + c16 * 8) =
            *(uint4*)(sm + 34816 + row * 272 + c16 * 16);
    }
}

// ---------------------------------------------------------------------------
// K3: pv. 512 threads, 16 warps; warp tile 16 rows x 32 cols
//   (wm = wid&7, wn = wid>>3). cp.async double-buffered over 16 k-tiles.
// smem (dynamic 217088): 2 stages [UH 0 / UL 34816 / VH 69632 / VL 87040],
//   stage 104448; FACS @208896.
// ---------------------------------------------------------------------------
constexpr int PV_STG = 104448;
constexpr int PV_UH = 0, PV_UL = 34816, PV_VH = 69632, PV_VL = 87040;
constexpr int PV_FACS = 208896;

__global__ __launch_bounds__(512) void pv_tc(float* __restrict__ attn)
{
    extern __shared__ char sm[];
    uint32_t sb = smem_u32(sm);
    int tid = threadIdx.x, lane = tid & 31, wid = tid >> 5;
    int qt = blockIdx.x, nh = blockIdx.y;
    int q0 = qt * 128;

    const __nv_bfloat16* vhp = g_vth + (long long)nh * 64 * P_;
    const __nv_bfloat16* vlp = g_vtl + (long long)nh * 64 * P_;
    long long ub = ((long long)nh << 22) + (long long)q0 * 2048;
    float* facs = (float*)(sm + PV_FACS);

    // prefetch tile 0 into stage 0
    {
        uint32_t st = sb;
        #pragma unroll
        for (int i = 0; i < 4; ++i) {
            int lin = i * 512 + tid;
            int row = lin >> 4, c16 = lin & 15;
            cpa16(st + PV_UH + row * 272 + c16 * 16,
                  g_uh + ub + (long long)row * 2048 + c16 * 8);
            cpa16(st + PV_UL + row * 272 + c16 * 16,
                  g_ul + ub + (long long)row * 2048 + c16 * 8);
        }
        #pragma unroll
        for (int i = 0; i < 2; ++i) {
            int lin = i * 512 + tid;
            int row = lin >> 4, c16 = lin & 15;
            cpa16(st + PV_VH + row * 272 + c16 * 16,
                  vhp + (long long)row * P_ + c16 * 8);
            cpa16(st + PV_VL + row * 272 + c16 * 16,
                  vlp + (long long)row * P_ + c16 * 8);
        }
        CP_COMMIT();
    }

    // softmax combine factors (overlaps with prefetch)
    if (tid < 128) {
        float pm[16];
        float M = -1e30f;
        #pragma unroll
        for (int t = 0; t < 16; ++t) {
            pm[t] = g_pm[(nh * 16 + t) * P_ + q0 + tid];
            M = fmaxf(M, pm[t]);
        }
        float L = 0.f, e[16];
        #pragma unroll
        for (int t = 0; t < 16; ++t) {
            e[t] = fexp(pm[t] - M);
            L += g_ps[(nh * 16 + t) * P_ + q0 + tid] * e[t];
        }
        float inv = 1.f / L;
        #pragma unroll
        for (int t = 0; t < 16; ++t) facs[tid * 16 + t] = e[t] * inv;
    }

    float* S = attn + ub;
    float acc[4][4] = {};
    int wm = wid & 7, wn = wid >> 3;   // 8 row-groups x 2 col-halves (32 each)
    uint32_t aoff = (uint32_t)(wm * 16 + (lane & 15)) * 272 + ((lane & 16) ? 16u : 0u);
    uint32_t boff = (uint32_t)(wn * 32 + (lane & 7) + ((lane & 16) ? 8 : 0)) * 272 +
                    ((lane & 8) ? 16u : 0u);
    int g = lane >> 2;

    #pragma unroll 1
    for (int kb = 0; kb < 16; ++kb) {
        if (kb + 1 < 16) {   // prefetch next tile
            uint32_t st = sb + ((kb + 1) & 1) * PV_STG;
            int k1 = (kb + 1) * 128;
            #pragma unroll
            for (int i = 0; i < 4; ++i) {
                int lin = i * 512 + tid;
                int row = lin >> 4, c16 = lin & 15;
                cpa16(st + PV_UH + row * 272 + c16 * 16,
                      g_uh + ub + (long long)row * 2048 + k1 + c16 * 8);
                cpa16(st + PV_UL + row * 272 + c16 * 16,
                      g_ul + ub + (long long)row * 2048 + k1 + c16 * 8);
            }
            #pragma unroll
            for (int i = 0; i < 2; ++i) {
                int lin = i * 512 + tid;
                int row = lin >> 4, c16 = lin & 15;
                cpa16(st + PV_VH + row * 272 + c16 * 16,
                      vhp + (long long)row * P_ + k1 + c16 * 8);
                cpa16(st + PV_VL + row * 272 + c16 * 16,
                      vlp + (long long)row * P_ + k1 + c16 * 8);
            }
            CP_COMMIT();
            CP_WAIT1();
        } else {
            CP_WAIT0();
        }
        __syncthreads();

        uint32_t st = sb + (kb & 1) * PV_STG;
        char*    stc = sm + (kb & 1) * PV_STG;

        // MMA: acc_t = U_tile @ V_tile (3 hi/lo passes), then rescale-accum
        float acc_t[4][4] = {};
        #pragma unroll
        for (int pass = 0; pass < 3; ++pass) {
            uint32_t Ab = st + (pass == 2 ? PV_UL : PV_UH);
            uint32_t Bb = st + (pass == 1 ? PV_VL : PV_VH);
            #pragma unroll
            for (int ks = 0; ks < 8; ++ks) {
                uint32_t af[4], bf2[2][4];
                ldsm4(af, Ab + aoff + ks * 32);
                #pragma unroll
                for (int np = 0; np < 2; ++np)
                    ldsm4(bf2[np], Bb + boff + np * 16 * 272 + ks * 32);
                #pragma unroll
                for (int ni = 0; ni < 4; ++ni)
                    mma16816(acc_t[ni], af,
                             bf2[ni >> 1][(ni & 1) * 2], bf2[ni >> 1][(ni & 1) * 2 + 1]);
            }
        }
        float c0 = facs[(wm * 16 + g) * 16 + kb];
        float c1 = facs[(wm * 16 + 8 + g) * 16 + kb];
        #pragma unroll
        for (int ni = 0; ni < 4; ++ni) {
            acc[ni][0] = fmaf(c0, acc_t[ni][0], acc[ni][0]);
            acc[ni][1] = fmaf(c0, acc_t[ni][1], acc[ni][1]);
            acc[ni][2] = fmaf(c1, acc_t[ni][2], acc[ni][2]);
            acc[ni][3] = fmaf(c1, acc_t[ni][3], acc[ni][3]);
        }

        // probs output: p = (uh+ul)*fac, streamed from smem
        int k0 = kb * 128;
        #pragma unroll 4
        for (int i = 0; i < 8; ++i) {
            int lin = i * 512 + tid;
            int row = lin >> 5, c4 = lin & 31;
            uint2 wh = *(uint2*)(stc + PV_UH + row * 272 + c4 * 8);
            uint2 wl = *(uint2*)(stc + PV_UL + row * 272 + c4 * 8);
            float fac = facs[row * 16 + kb];
            float2 h0 = bf2f(wh.x), h1 = bf2f(wh.y);
            float2 l0 = bf2f(wl.x), l1 = bf2f(wl.y);
            *(float4*)&S[(long long)row * 2048 + k0 + c4 * 4] =
                make_float4((h0.x + l0.x) * fac, (h0.y + l0.y) * fac,
                            (h1.x + l1.x) * fac, (h1.y + l1.y) * fac);
        }
        __syncthreads();
    }

    // Epilogue: stage O fp32, then bf16 hi/lo to g_oh/g_ol [n][p][512]
    int tg = lane & 3;
    float* Ost = (float*)sm;  // stride 68 floats (reuse stage 0)
    #pragma unroll
    for (int h = 0; h < 2; ++h) {
        int row = wm * 16 + h * 8 + g;
        #pragma unroll
        for (int ni = 0; ni < 4; ++ni)
            *(float2*)&Ost[row * 68 + wn * 32 + ni * 8 + tg * 2] =
                make_float2(acc[ni][h * 2], acc[ni][h * 2 + 1]);
    }
    __syncthreads();
    int n = nh >> 3, h = nh & 7;
    #pragma unroll
    for (int i = 0; i < 2; ++i) {
        int lin = i * 512 + tid;
        int row = lin >> 3, c8 = lin & 7;
        long long dst = ((long long)(n * P_ + q0 + row)) * 512 + h * 64 + c8 * 8;
        const float* src = &Ost[row * 68 + c8 * 8];
        float v0 = src[0], v1 = src[1], v2 = src[2], v3 = src[3];
        float v4 = src[4], v5 = src[5], v6 = src[6], v7 = src[7];
        __nv_bfloat16 b0 = __float2bfloat16(v0), b1 = __float2bfloat16(v1);
        __nv_bfloat16 b2 = __float2bfloat16(v2), b3 = __float2bfloat16(v3);
        __nv_bfloat16 b4 = __float2bfloat16(v4), b5 = __float2bfloat16(v5);
        __nv_bfloat16 b6 = __float2bfloat16(v6), b7 = __float2bfloat16(v7);
        *(ushort4*)&g_oh[dst]     = make_ushort4(bfu(b0), bfu(b1), bfu(b2), bfu(b3));
        *(ushort4*)&g_oh[dst + 4] = make_ushort4(bfu(b4), bfu(b5), bfu(b6), bfu(b7));
        *(ushort4*)&g_ol[dst] = make_ushort4(
            bfu(__float2bfloat16(v0 - __bfloat162float(b0))),
            bfu(__float2bfloat16(v1 - __bfloat162float(b1))),
            bfu(__float2bfloat16(v2 - __bfloat162float(b2))),
            bfu(__float2bfloat16(v3 - __bfloat162float(b3))));
        *(ushort4*)&g_ol[dst + 4] = make_ushort4(
            bfu(__float2bfloat16(v4 - __bfloat162float(b4))),
            bfu(__float2bfloat16(v5 - __bfloat162float(b5))),
            bfu(__float2bfloat16(v6 - __bfloat162float(b6))),
            bfu(__float2bfloat16(v7 - __bfloat162float(b7))));
    }
}

// ---------------------------------------------------------------------------
// K4: out = O_flat @ Wo^T + bo via mma.sync bf16 hi/lo. 512 threads.
// Tile 128 x 128, k-chunks of 64; warp tile 16 x 64 (wm = wid>>1, wn = wid&1).
// smem (dynamic 73728): AH 0 / AL 18432 / BH 36864 / BL 55296 (stride 144B).
// ---------------------------------------------------------------------------
__global__ __launch_bounds__(512) void outproj_tc(
    const float* __restrict__ bo,
    float* __restrict__ out)
{
    extern __shared__ char sm[];
    uint32_t sb = smem_u32(sm);
    int tid = threadIdx.x, lane = tid & 31, wid = tid >> 5;
    int ct = blockIdx.x, rt = blockIdx.y;
    int r0 = rt * 128, c0 = ct * 128;

    const int AH = 0, AL = 18432, BH = 36864, BL = 55296;
    int wm = wid >> 1, wn = wid & 1;
    float acc[8][4] = {};
    uint32_t aoff = (uint32_t)(wm * 16 + (lane & 15)) * TSB + ((lane & 16) ? 16u : 0u);
    uint32_t boff = (uint32_t)(wn * 64 + (lane & 7) + ((lane & 16) ? 8 : 0)) * TSB +
                    ((lane & 8) ? 16u : 0u);

    #pragma unroll 1
    for (int kb = 0; kb < 8; ++kb) {
        int k0 = kb * 64;
        #pragma unroll
        for (int i = 0; i < 2; ++i) {
            int lin = i * 512 + tid;
            int row = lin >> 3, c8 = lin & 7;
            long long asrc = (long long)(r0 + row) * 512 + k0 + c8 * 8;
            long long bsrc = (long long)(c0 + row) * 512 + k0 + c8 * 8;
            *(uint4*)(sm + AH + row * TSB + c8 * 16) = *(const uint4*)(g_oh + asrc);
            *(uint4*)(sm + AL + row * TSB + c8 * 16) = *(const uint4*)(g_ol + asrc);
            *(uint4*)(sm + BH + row * TSB + c8 * 16) = *(const uint4*)(g_woh + bsrc);
            *(uint4*)(sm + BL + row * TSB + c8 * 16) = *(const uint4*)(g_wol + bsrc);
        }
        __syncthreads();

        #pragma unroll
        for (int pass = 0; pass < 3; ++pass) {
            uint32_t Ab = sb + (pass == 2 ? AL : AH);
            uint32_t Bb = sb + (pass == 1 ? BL : BH);
            #pragma unroll
            for (int ks = 0; ks < 4; ++ks) {
                uint32_t af[4], bf2[4][4];
                ldsm4(af, Ab + aoff + ks * 32);
                #pragma unroll
                for (int np = 0; np < 4; ++np)
                    ldsm4(bf2[np], Bb + boff + np * 16 * TSB + ks * 32);
                #pragma unroll
                for (int ni = 0; ni < 8; ++ni)
                    mma16816(acc[ni], af,
                             bf2[ni >> 1][(ni & 1) * 2], bf2[ni >> 1][(ni & 1) * 2 + 1]);
            }
        }
        __syncthreads();
    }

    int g = lane >> 2, tg = lane & 3;
    #pragma unroll
    for (int ni = 0; ni < 8; ++ni) {
        int col = wn * 64 + ni * 8 + tg * 2;
        float2 bb = *(const float2*)&bo[c0 + col];
        #pragma unroll
        for (int h = 0; h < 2; ++h) {
            int row = wm * 16 + h * 8 + g;
            *(float2*)&out[(long long)(r0 + row) * 512 + c0 + col] =
                make_float2(acc[ni][h * 2] + bb.x,
                            acc[ni][h * 2 + 1] + bb.y);
        }
    }
}

// ---------------------------------------------------------------------------
extern "C" void kernel_launch(void* const* d_in, const int* in_sizes, int n_in,
                              void* d_out, int out_size)
{
    const float* xyz = (const float*)d_in[0];
    const float* Wq  = (const float*)d_in[1];
    const float* Wk  = (const float*)d_in[2];
    const float* Wv  = (const float*)d_in[3];
    const float* Wo  = (const float*)d_in[4];
    const float* bo  = (const float*)d_in[5];
    float* out = (float*)d_out;

    float* attn;
    if ((long long)out_size >= NPD_ + NHPP_) {
        attn = out + NPD_;
    } else {
        void* p = nullptr;
        cudaGetSymbolAddress(&p, g_attn);
        attn = (float*)p;
    }

    cudaFuncSetAttribute(scores_tc,  cudaFuncAttributeMaxDynamicSharedMemorySize, 73728);
    cudaFuncSetAttribute(pv_tc,      cudaFuncAttributeMaxDynamicSharedMemorySize, 217088);
    cudaFuncSetAttribute(outproj_tc, cudaFuncAttributeMaxDynamicSharedMemorySize, 73728);

    wo_split_kernel<<<(D_ * D_ + 255) / 256, 256>>>(Wo);
    qkv_kernel<<<dim3(P_ / 64, NH_), 256>>>(xyz, Wq, Wk, Wv);
    scores_tc<<<dim3(16, 16, NH_), 512, 73728>>>();
    pv_tc<<<dim3(16, NH_), 512, 217088>>>(attn);
    outproj_tc<<<dim3(4, 64), 512, 73728>>>(bo, out);
}

// round 13
// speedup vs baseline: 1.1422x; 1.1422x over previous
#include <cuda_runtime.h>
#include <cuda_bf16.h>
#include <stdint.h>
#include <math.h>

// Problem constants
constexpr int N_  = 4;
constexpr int P_  = 2048;
constexpr int D_  = 512;
constexpr int H_  = 8;
constexpr int HD_ = 64;
constexpr int NH_ = N_ * H_;                              // 32
constexpr long long NPD_  = (long long)N_ * P_ * D_;      // 4194304
constexpr long long NHPP_ = (long long)N_ * H_ * P_ * P_; // 134217728
constexpr float SCALE_ = 0.044194173824159216f;           // 1/sqrt(512)

// ---------------------------------------------------------------------------
// Scratch (device globals; allocation-free per harness rules)
// ---------------------------------------------------------------------------
__device__ __align__(16) __nv_bfloat16 g_qh[NH_ * P_ * HD_];
__device__ __align__(16) __nv_bfloat16 g_ql[NH_ * P_ * HD_];
__device__ __align__(16) __nv_bfloat16 g_kh[NH_ * P_ * HD_];
__device__ __align__(16) __nv_bfloat16 g_kl[NH_ * P_ * HD_];
__device__ __align__(16) __nv_bfloat16 g_vth[NH_ * HD_ * P_]; // V^T [nh][e][p]
__device__ __align__(16) __nv_bfloat16 g_vtl[NH_ * HD_ * P_];
__device__ __align__(16) __nv_bfloat16 g_uh[NHPP_];  // u = exp(S - m_tile) hi
__device__ __align__(16) __nv_bfloat16 g_ul[NHPP_];  // u lo
__device__ __align__(16) __nv_bfloat16 g_oh[NPD_];   // O flat [n][p][512] hi
__device__ __align__(16) __nv_bfloat16 g_ol[NPD_];
__device__ __align__(16) __nv_bfloat16 g_woh[D_ * D_];
__device__ __align__(16) __nv_bfloat16 g_wol[D_ * D_];
__device__ float g_pm[NH_ * 32 * P_];     // per-64-ktile row max partial
__device__ float g_ps[NH_ * 32 * P_];     // per-64-ktile row sumexp partial
__device__ float g_attn[NHPP_];           // fallback if attention not in d_out

// ---------------------------------------------------------------------------
// Helpers
// ---------------------------------------------------------------------------
__device__ __forceinline__ uint32_t smem_u32(const void* p) {
    uint32_t a;
    asm("{ .reg .u64 t; cvta.to.shared.u64 t, %1; cvt.u32.u64 %0, t; }"
        : "=r"(a) : "l"(p));
    return a;
}

__device__ __forceinline__ void ldsm4(uint32_t* r, uint32_t a) {
    asm volatile("ldmatrix.sync.aligned.m8n8.x4.shared.b16 {%0,%1,%2,%3}, [%4];"
                 : "=r"(r[0]), "=r"(r[1]), "=r"(r[2]), "=r"(r[3]) : "r"(a));
}

__device__ __forceinline__ void mma16816(float* d, const uint32_t* a,
                                         uint32_t b0, uint32_t b1) {
    asm volatile("mma.sync.aligned.m16n8k16.row.col.f32.bf16.bf16.f32 "
                 "{%0,%1,%2,%3},{%4,%5,%6,%7},{%8,%9},{%0,%1,%2,%3};"
                 : "+f"(d[0]), "+f"(d[1]), "+f"(d[2]), "+f"(d[3])
                 : "r"(a[0]), "r"(a[1]), "r"(a[2]), "r"(a[3]), "r"(b0), "r"(b1));
}

__device__ __forceinline__ void cpa16(uint32_t d, const void* s) {
    asm volatile("cp.async.cg.shared.global [%0], [%1], 16;" :: "r"(d), "l"(s));
}
#define CP_COMMIT() asm volatile("cp.async.commit_group;" ::: "memory")
#define CP_WAIT1()  asm volatile("cp.async.wait_group 1;" ::: "memory")
#define CP_WAIT0()  asm volatile("cp.async.wait_group 0;" ::: "memory")

// Fast exp on the FFMA pipe (valid for x <= 0; ~1e-7 rel err). Avoids MUFU.
__device__ __forceinline__ float fexp(float x) {
    float t = x * 1.4426950408889634f;
    t = fmaxf(t, -120.f);
    float z = t + 12582912.f;
    int   n = __float_as_int(z) - 0x4B400000;
    float f = t - (z - 12582912.f);
    float r = 1.5403530393381609e-4f;
    r = fmaf(r, f, 1.3333558146428443e-3f);
    r = fmaf(r, f, 9.6181291076284772e-3f);
    r = fmaf(r, f, 5.5504108664821580e-2f);
    r = fmaf(r, f, 2.4022650695910072e-1f);
    r = fmaf(r, f, 6.9314718055994531e-1f);
    r = fmaf(r, f, 1.0f);
    return __int_as_float(__float_as_int(r) + (n << 23));
}

__device__ __forceinline__ unsigned short bfu(__nv_bfloat16 b) {
    return __bfloat16_as_ushort(b);
}
__device__ __forceinline__ uint32_t packbf(float a, float b) {
    return (uint32_t)bfu(__float2bfloat16(a)) |
           ((uint32_t)bfu(__float2bfloat16(b)) << 16);
}
__device__ __forceinline__ float2 bf2f(uint32_t w) {
    __nv_bfloat162 b = *reinterpret_cast<__nv_bfloat162*>(&w);
    return make_float2(__bfloat162float(b.x), __bfloat162float(b.y));
}

// ---------------------------------------------------------------------------
// K0: split Wo into bf16 hi/lo
// ---------------------------------------------------------------------------
__global__ __launch_bounds__(256) void wo_split_kernel(const float* __restrict__ Wo)
{
    int i = blockIdx.x * 256 + threadIdx.x;
    if (i < D_ * D_) {
        float v = Wo[i];
        __nv_bfloat16 hb = __float2bfloat16(v);
        g_woh[i] = hb;
        g_wol[i] = __float2bfloat16(v - __bfloat162float(hb));
    }
}

// ---------------------------------------------------------------------------
// K1: QKV projection (fp32 FFMA) -> bf16 hi/lo outputs.
// ---------------------------------------------------------------------------
__global__ __launch_bounds__(256) void qkv_kernel(
    const float* __restrict__ xyz,
    const float* __restrict__ Wq,
    const float* __restrict__ Wk,
    const float* __restrict__ Wv)
{
    __shared__ float xs[64][65];
    __shared__ float Wt[64][68];

    int ptile = blockIdx.x, nh = blockIdx.y;
    int n = nh / H_, h = nh % H_;
    int p0 = ptile * 64;
    int tid = threadIdx.x;

    for (int i = tid; i < 4096; i += 256) {
        int row = i >> 6, dd = i & 63;
        xs[row][dd] = xyz[(n * P_ + p0 + row) * D_ + h * HD_ + dd];
    }

    int tx = tid & 15, ty = tid >> 4;
    int r = ty * 4, c = tx * 4;
    const float* Ws[3] = {Wq, Wk, Wv};

    for (int m = 0; m < 3; ++m) {
        __syncthreads();
        const float* W = Ws[m];
        for (int i = tid; i < 4096; i += 256) {
            int e = i >> 6, dd = i & 63;
            Wt[dd][e] = W[i];
        }
        __syncthreads();

        float acc[4][4] = {};
        #pragma unroll
        for (int dd = 0; dd < 64; ++dd) {
            float a0 = xs[r + 0][dd], a1 = xs[r + 1][dd];
            float a2 = xs[r + 2][dd], a3 = xs[r + 3][dd];
            float4 b = *(const float4*)&Wt[dd][c];
            acc[0][0] += a0 * b.x; acc[0][1] += a0 * b.y; acc[0][2] += a0 * b.z; acc[0][3] += a0 * b.w;
            acc[1][0] += a1 * b.x; acc[1][1] += a1 * b.y; acc[1][2] += a1 * b.z; acc[1][3] += a1 * b.w;
            acc[2][0] += a2 * b.x; acc[2][1] += a2 * b.y; acc[2][2] += a2 * b.z; acc[2][3] += a2 * b.w;
            acc[3][0] += a3 * b.x; acc[3][1] += a3 * b.y; acc[3][2] += a3 * b.z; acc[3][3] += a3 * b.w;
        }

        if (m < 2) {
            float sc = (m == 0) ? SCALE_ : 1.0f;
            __nv_bfloat16* Ah = (m == 0) ? g_qh : g_kh;
            __nv_bfloat16* Al = (m == 0) ? g_ql : g_kl;
            #pragma unroll
            for (int i = 0; i < 4; ++i) {
                long long idx = ((long long)(nh * P_ + p0 + r + i)) * 64 + c;
                float v0 = acc[i][0] * sc, v1 = acc[i][1] * sc;
                float v2 = acc[i][2] * sc, v3 = acc[i][3] * sc;
                __nv_bfloat16 h0 = __float2bfloat16(v0), h1 = __float2bfloat16(v1);
                __nv_bfloat16 h2 = __float2bfloat16(v2), h3 = __float2bfloat16(v3);
                *(ushort4*)&Ah[idx] = make_ushort4(bfu(h0), bfu(h1), bfu(h2), bfu(h3));
                *(ushort4*)&Al[idx] = make_ushort4(
                    bfu(__float2bfloat16(v0 - __bfloat162float(h0))),
                    bfu(__float2bfloat16(v1 - __bfloat162float(h1))),
                    bfu(__float2bfloat16(v2 - __bfloat162float(h2))),
                    bfu(__float2bfloat16(v3 - __bfloat162float(h3))));
            }
        } else {
            __syncthreads();
            #pragma unroll
            for (int i = 0; i < 4; ++i)
                #pragma unroll
                for (int j = 0; j < 4; ++j)
                    xs[c + j][r + i] = acc[i][j];
            __syncthreads();
            for (int i = tid; i < 4096; i += 256) {
                int e = i >> 6, pp = i & 63;
                float v = xs[e][pp];
                __nv_bfloat16 hb = __float2bfloat16(v);
                long long idx = (long long)(nh * 64 + e) * P_ + p0 + pp;
                g_vth[idx] = hb;
                g_vtl[idx] = __float2bfloat16(v - __bfloat162float(hb));
            }
        }
    }
}

// ---------------------------------------------------------------------------
// K2: S = QK^T via mma.sync bf16 hi/lo. CTA tile 128q x 64k, 256 thr, 8 warps,
//   warp tile 16x64 (wm = wid). Stats fully in-warp (rows owned by one warp).
//   2 CTAs/SM via __launch_bounds__(256,2).
// smem (dynamic 55296, stride 144B): QH 0 / QL 18432 / KH 36864 / KL 46080.
//   Reused stage: u hi @0, u lo @18432 (stride 144).
// ---------------------------------------------------------------------------
constexpr int TS6 = 144;

__global__ __launch_bounds__(256, 2) void scores_tc()
{
    extern __shared__ char sm[];
    uint32_t sb = smem_u32(sm);
    int tid = threadIdx.x, lane = tid & 31, wid = tid >> 5;
    int kt = blockIdx.x, qt = blockIdx.y, nh = blockIdx.z;
    int q0 = qt * 128, k0 = kt * 64;

    const int QH = 0, QL = 18432, KH = 36864, KL = 46080;
    {
        const __nv_bfloat16* qh = g_qh + (long long)(nh * P_ + q0) * 64;
        const __nv_bfloat16* ql = g_ql + (long long)(nh * P_ + q0) * 64;
        const __nv_bfloat16* kh = g_kh + (long long)(nh * P_ + k0) * 64;
        const __nv_bfloat16* kl = g_kl + (long long)(nh * P_ + k0) * 64;
        #pragma unroll
        for (int i = 0; i < 4; ++i) {
            int lin = i * 256 + tid;
            int row = lin >> 3, c8 = lin & 7;
            *(uint4*)(sm + QH + row * TS6 + c8 * 16) = *(const uint4*)(qh + row * 64 + c8 * 8);
            *(uint4*)(sm + QL + row * TS6 + c8 * 16) = *(const uint4*)(ql + row * 64 + c8 * 8);
        }
        #pragma unroll
        for (int i = 0; i < 2; ++i) {
            int lin = i * 256 + tid;
            int row = lin >> 3, c8 = lin & 7;
            *(uint4*)(sm + KH + row * TS6 + c8 * 16) = *(const uint4*)(kh + row * 64 + c8 * 8);
            *(uint4*)(sm + KL + row * TS6 + c8 * 16) = *(const uint4*)(kl + row * 64 + c8 * 8);
        }
    }
    __syncthreads();

    float acc[8][4] = {};
    uint32_t aoff = (uint32_t)(wid * 16 + (lane & 15)) * TS6 + ((lane & 16) ? 16u : 0u);
    uint32_t boff = (uint32_t)((lane & 7) + ((lane & 16) ? 8 : 0)) * TS6 +
                    ((lane & 8) ? 16u : 0u);

    #pragma unroll
    for (int pass = 0; pass < 3; ++pass) {
        uint32_t Ab = sb + (pass == 2 ? QL : QH);
        uint32_t Bb = sb + (pass == 1 ? KL : KH);
        #pragma unroll
        for (int ks = 0; ks < 4; ++ks) {
            uint32_t af[4], bf2[4][4];
            ldsm4(af, Ab + aoff + ks * 32);
            #pragma unroll
            for (int np = 0; np < 4; ++np)
                ldsm4(bf2[np], Bb + boff + np * 16 * TS6 + ks * 32);
            #pragma unroll
            for (int ni = 0; ni < 8; ++ni)
                mma16816(acc[ni], af,
                         bf2[ni >> 1][(ni & 1) * 2], bf2[ni >> 1][(ni & 1) * 2 + 1]);
        }
    }
    __syncthreads();   // operands dead; smem reused for u stage

    int g = lane >> 2, tg = lane & 3;
    long long sbase = (long long)(nh * 32 + kt) * P_ + q0;

    #pragma unroll
    for (int h = 0; h < 2; ++h) {
        int row = wid * 16 + h * 8 + g;
        // in-warp row max (row fully owned by 4-lane group)
        float m = -1e30f;
        #pragma unroll
        for (int ni = 0; ni < 8; ++ni)
            m = fmaxf(m, fmaxf(acc[ni][h * 2], acc[ni][h * 2 + 1]));
        m = fmaxf(m, __shfl_xor_sync(0xFFFFFFFFu, m, 1));
        m = fmaxf(m, __shfl_xor_sync(0xFFFFFFFFu, m, 2));
        // exp + split + stage
        float s = 0.f;
        #pragma unroll
        for (int ni = 0; ni < 8; ++ni) {
            float u0 = fexp(acc[ni][h * 2] - m);
            float u1 = fexp(acc[ni][h * 2 + 1] - m);
            s += u0 + u1;
            int col = ni * 8 + tg * 2;
            __nv_bfloat16 h0 = __float2bfloat16(u0);
            __nv_bfloat16 h1 = __float2bfloat16(u1);
            uint32_t ph = (uint32_t)bfu(h0) | ((uint32_t)bfu(h1) << 16);
            uint32_t pl = packbf(u0 - __bfloat162float(h0),
                                 u1 - __bfloat162float(h1));
            *(uint32_t*)(sm + 0     + row * TS6 + col * 2) = ph;
            *(uint32_t*)(sm + 18432 + row * TS6 + col * 2) = pl;
        }
        s += __shfl_xor_sync(0xFFFFFFFFu, s, 1);
        s += __shfl_xor_sync(0xFFFFFFFFu, s, 2);
        if (tg == 0) {
            g_pm[sbase + row] = m;
            g_ps[sbase + row] = s;
        }
    }
    __syncthreads();

    long long ub = ((long long)nh << 22) + (long long)q0 * 2048 + k0;
    #pragma unroll
    for (int i = 0; i < 4; ++i) {
        int lin = i * 256 + tid;
        int row = lin >> 3, c8 = lin & 7;
        *(uint4*)(g_uh + ub + (long long)row * 2048 + c8 * 8) =
            *(uint4*)(sm + 0 + row * TS6 + c8 * 16);
        *(uint4*)(g_ul + ub + (long long)row * 2048 + c8 * 8) =
            *(uint4*)(sm + 18432 + row * TS6 + c8 * 16);
    }
}

// ---------------------------------------------------------------------------
// K3: pv. 256 thr, 8 fat warps (warp tile 16 rows x 64 cols).
//   32 k-tiles of 64; 3-stage cp.async pipeline, ONE sync per iteration.
// smem (dynamic 182272): stages s*55296: UH+0 / UL+18432 / VH+36864 /
//   VL+46080 (stride 144). FACS @165888 (128 x 32 f32).
// ---------------------------------------------------------------------------
constexpr int PV_STG = 55296;
constexpr int PV_UH = 0, PV_UL = 18432, PV_VH = 36864, PV_VL = 46080;
constexpr int PV_FACS = 165888;

__device__ __forceinline__ void pv_prefetch(
    uint32_t st, const __nv_bfloat16* uh, const __nv_bfloat16* ul,
    const __nv_bfloat16* vh, const __nv_bfloat16* vl, int k0, int tid)
{
    #pragma unroll
    for (int i = 0; i < 4; ++i) {
        int lin = i * 256 + tid;
        int row = lin >> 3, c8 = lin & 7;
        cpa16(st + PV_UH + row * TS6 + c8 * 16, uh + (long long)row * 2048 + k0 + c8 * 8);
        cpa16(st + PV_UL + row * TS6 + c8 * 16, ul + (long long)row * 2048 + k0 + c8 * 8);
    }
    #pragma unroll
    for (int i = 0; i < 2; ++i) {
        int lin = i * 256 + tid;
        int row = lin >> 3, c8 = lin & 7;
        cpa16(st + PV_VH + row * TS6 + c8 * 16, vh + (long long)row * P_ + k0 + c8 * 8);
        cpa16(st + PV_VL + row * TS6 + c8 * 16, vl + (long long)row * P_ + k0 + c8 * 8);
    }
    CP_COMMIT();
}

__global__ __launch_bounds__(256) void pv_tc(float* __restrict__ attn)
{
    extern __shared__ char sm[];
    uint32_t sb = smem_u32(sm);
    int tid = threadIdx.x, lane = tid & 31, wid = tid >> 5;
    int qt = blockIdx.x, nh = blockIdx.y;
    int q0 = qt * 128;

    const __nv_bfloat16* vhp = g_vth + (long long)nh * 64 * P_;
    const __nv_bfloat16* vlp = g_vtl + (long long)nh * 64 * P_;
    long long ub = ((long long)nh << 22) + (long long)q0 * 2048;
    const __nv_bfloat16* uhp = g_uh + ub;
    const __nv_bfloat16* ulp = g_ul + ub;
    float* facs = (float*)(sm + PV_FACS);

    // prologue: prefetch tiles 0,1
    pv_prefetch(sb,          uhp, ulp, vhp, vlp, 0,  tid);
    pv_prefetch(sb + PV_STG, uhp, ulp, vhp, vlp, 64, tid);

    // softmax combine factors (overlaps prefetch)
    if (tid < 128) {
        float pm[32];
        float M = -1e30f;
        #pragma unroll
        for (int t = 0; t < 32; ++t) {
            pm[t] = g_pm[(long long)(nh * 32 + t) * P_ + q0 + tid];
            M = fmaxf(M, pm[t]);
        }
        float L = 0.f;
        #pragma unroll
        for (int t = 0; t < 32; ++t) {
            float e = fexp(pm[t] - M);
            L += g_ps[(long long)(nh * 32 + t) * P_ + q0 + tid] * e;
            facs[tid * 32 + t] = e;
        }
        float inv = 1.f / L;
        #pragma unroll
        for (int t = 0; t < 32; ++t) facs[tid * 32 + t] *= inv;
    }

    float* S = attn + ub;
    float acc[8][4] = {};
    uint32_t aoff = (uint32_t)(wid * 16 + (lane & 15)) * TS6 + ((lane & 16) ? 16u : 0u);
    uint32_t boff = (uint32_t)((lane & 7) + ((lane & 16) ? 8 : 0)) * TS6 +
                    ((lane & 8) ? 16u : 0u);
    int g = lane >> 2;

    #pragma unroll 1
    for (int kb = 0; kb < 32; ++kb) {
        if (kb < 31) { CP_WAIT1(); } else { CP_WAIT0(); }
        __syncthreads();   // tile kb ready in all threads; stage (kb+2)%3 free

        if (kb + 2 < 32)
            pv_prefetch(sb + ((kb + 2) % 3) * PV_STG, uhp, ulp, vhp, vlp,
                        (kb + 2) * 64, tid);

        uint32_t st = sb + (kb % 3) * PV_STG;
        char*    stc = sm + (kb % 3) * PV_STG;

        // acc_t = U_tile @ V_tile (3 hi/lo passes), then rescale-accumulate
        float acc_t[8][4] = {};
        #pragma unroll
        for (int pass = 0; pass < 3; ++pass) {
            uint32_t Ab = st + (pass == 2 ? PV_UL : PV_UH);
            uint32_t Bb = st + (pass == 1 ? PV_VL : PV_VH);
            #pragma unroll
            for (int ks = 0; ks < 4; ++ks) {
                uint32_t af[4], bf2[4][4];
                ldsm4(af, Ab + aoff + ks * 32);
                #pragma unroll
                for (int np = 0; np < 4; ++np)
                    ldsm4(bf2[np], Bb + boff + np * 16 * TS6 + ks * 32);
                #pragma unroll
                for (int ni = 0; ni < 8; ++ni)
                    mma16816(acc_t[ni], af,
                             bf2[ni >> 1][(ni & 1) * 2], bf2[ni >> 1][(ni & 1) * 2 + 1]);
            }
        }
        float c0 = facs[(wid * 16 + g) * 32 + kb];
        float c1 = facs[(wid * 16 + 8 + g) * 32 + kb];
        #pragma unroll
        for (int ni = 0; ni < 8; ++ni) {
            acc[ni][0] = fmaf(c0, acc_t[ni][0], acc[ni][0]);
            acc[ni][1] = fmaf(c0, acc_t[ni][1], acc[ni][1]);
            acc[ni][2] = fmaf(c1, acc_t[ni][2], acc[ni][2]);
            acc[ni][3] = fmaf(c1, acc_t[ni][3], acc[ni][3]);
        }

        // probs output: p = (uh+ul)*fac
        int k0 = kb * 64;
        #pragma unroll 4
        for (int i = 0; i < 8; ++i) {
            int lin = i * 256 + tid;
            int row = lin >> 4, c4 = lin & 15;
            uint2 wh = *(uint2*)(stc + PV_UH + row * TS6 + c4 * 8);
            uint2 wl = *(uint2*)(stc + PV_UL + row * TS6 + c4 * 8);
            float fac = facs[row * 32 + kb];
            float2 h0 = bf2f(wh.x), h1 = bf2f(wh.y);
            float2 l0 = bf2f(wl.x), l1 = bf2f(wl.y);
            *(float4*)&S[(long long)row * 2048 + k0 + c4 * 4] =
                make_float4((h0.x + l0.x) * fac, (h0.y + l0.y) * fac,
                            (h1.x + l1.x) * fac, (h1.y + l1.y) * fac);
        }
    }

    // Epilogue: stage O fp32 in smem (stage 0 region), bf16 hi/lo to g_oh/g_ol
    int tg = lane & 3;
    float* Ost = (float*)sm;  // stride 68 floats
    __syncthreads();
    #pragma unroll
    for (int h = 0; h < 2; ++h) {
        int row = wid * 16 + h * 8 + g;
        #pragma unroll
        for (int ni = 0; ni < 8; ++ni)
            *(float2*)&Ost[row * 68 + ni * 8 + tg * 2] =
                make_float2(acc[ni][h * 2], acc[ni][h * 2 + 1]);
    }
    __syncthreads();
    int n = nh >> 3, h = nh & 7;
    #pragma unroll
    for (int i = 0; i < 4; ++i) {
        int lin = i * 256 + tid;
        int row = lin >> 3, c8 = lin & 7;
        long long dst = ((long long)(n * P_ + q0 + row)) * 512 + h * 64 + c8 * 8;
        const float* src = &Ost[row * 68 + c8 * 8];
        float v0 = src[0], v1 = src[1], v2 = src[2], v3 = src[3];
        float v4 = src[4], v5 = src[5], v6 = src[6], v7 = src[7];
        __nv_bfloat16 b0 = __float2bfloat16(v0), b1 = __float2bfloat16(v1);
        __nv_bfloat16 b2 = __float2bfloat16(v2), b3 = __float2bfloat16(v3);
        __nv_bfloat16 b4 = __float2bfloat16(v4), b5 = __float2bfloat16(v5);
        __nv_bfloat16 b6 = __float2bfloat16(v6), b7 = __float2bfloat16(v7);
        *(ushort4*)&g_oh[dst]     = make_ushort4(bfu(b0), bfu(b1), bfu(b2), bfu(b3));
        *(ushort4*)&g_oh[dst + 4] = make_ushort4(bfu(b4), bfu(b5), bfu(b6), bfu(b7));
        *(ushort4*)&g_ol[dst] = make_ushort4(
            bfu(__float2bfloat16(v0 - __bfloat162float(b0))),
            bfu(__float2bfloat16(v1 - __bfloat162float(b1))),
            bfu(__float2bfloat16(v2 - __bfloat162float(b2))),
            bfu(__float2bfloat16(v3 - __bfloat162float(b3))));
        *(ushort4*)&g_ol[dst + 4] = make_ushort4(
            bfu(__float2bfloat16(v4 - __bfloat162float(b4))),
            bfu(__float2bfloat16(v5 - __bfloat162float(b5))),
            bfu(__float2bfloat16(v6 - __bfloat162float(b6))),
            bfu(__float2bfloat16(v7 - __bfloat162float(b7))));
    }
}

// ---------------------------------------------------------------------------
// K4: out = O_flat @ Wo^T + bo via mma.sync bf16 hi/lo. 256 threads (round-7).
// Tile 128 x 128, k-chunks of 64; warp tile 32 x 64 (wm = wid>>1, wn = wid&1).
// smem (dynamic 73728): AH 0 / AL 18432 / BH 36864 / BL 55296 (stride 144B).
// ---------------------------------------------------------------------------
__global__ __launch_bounds__(256) void outproj_tc(
    const float* __restrict__ bo,
    float* __restrict__ out)
{
    extern __shared__ char sm[];
    uint32_t sb = smem_u32(sm);
    int tid = threadIdx.x, lane = tid & 31, wid = tid >> 5;
    int ct = blockIdx.x, rt = blockIdx.y;
    int r0 = rt * 128, c0 = ct * 128;

    const int AH = 0, AL = 18432, BH = 36864, BL = 55296;
    int wm = wid >> 1, wn = wid & 1;
    float acc[2][8][4] = {};
    uint32_t aoff = (uint32_t)(wm * 32 + (lane & 15)) * TS6 + ((lane & 16) ? 16u : 0u);
    uint32_t boff = (uint32_t)(wn * 64 + (lane & 7) + ((lane & 16) ? 8 : 0)) * TS6 +
                    ((lane & 8) ? 16u : 0u);

    #pragma unroll 1
    for (int kb = 0; kb < 8; ++kb) {
        int k0 = kb * 64;
        #pragma unroll
        for (int i = 0; i < 4; ++i) {
            int lin = i * 256 + tid;
            int row = lin >> 3, c8 = lin & 7;
            long long asrc = (long long)(r0 + row) * 512 + k0 + c8 * 8;
            long long bsrc = (long long)(c0 + row) * 512 + k0 + c8 * 8;
            *(uint4*)(sm + AH + row * TS6 + c8 * 16) = *(const uint4*)(g_oh + asrc);
            *(uint4*)(sm + AL + row * TS6 + c8 * 16) = *(const uint4*)(g_ol + asrc);
            *(uint4*)(sm + BH + row * TS6 + c8 * 16) = *(const uint4*)(g_woh + bsrc);
            *(uint4*)(sm + BL + row * TS6 + c8 * 16) = *(const uint4*)(g_wol + bsrc);
        }
        __syncthreads();

        #pragma unroll
        for (int pass = 0; pass < 3; ++pass) {
            uint32_t Ab = sb + (pass == 2 ? AL : AH);
            uint32_t Bb = sb + (pass == 1 ? BL : BH);
            #pragma unroll
            for (int ks = 0; ks < 4; ++ks) {
                uint32_t af[2][4], bf2[4][4];
                ldsm4(af[0], Ab + aoff + ks * 32);
                ldsm4(af[1], Ab + aoff + 16 * TS6 + ks * 32);
                #pragma unroll
                for (int np = 0; np < 4; ++np)
                    ldsm4(bf2[np], Bb + boff + np * 16 * TS6 + ks * 32);
                #pragma unroll
                for (int mi = 0; mi < 2; ++mi)
                    #pragma unroll
                    for (int ni = 0; ni < 8; ++ni)
                        mma16816(acc[mi][ni], af[mi],
                                 bf2[ni >> 1][(ni & 1) * 2], bf2[ni >> 1][(ni & 1) * 2 + 1]);
            }
        }
        __syncthreads();
    }

    int g = lane >> 2, tg = lane & 3;
    #pragma unroll
    for (int ni = 0; ni < 8; ++ni) {
        int col = wn * 64 + ni * 8 + tg * 2;
        float2 bb = *(const float2*)&bo[c0 + col];
        #pragma unroll
        for (int mi = 0; mi < 2; ++mi)
            #pragma unroll
            for (int h = 0; h < 2; ++h) {
                int row = wm * 32 + mi * 16 + h * 8 + g;
                *(float2*)&out[(long long)(r0 + row) * 512 + c0 + col] =
                    make_float2(acc[mi][ni][h * 2] + bb.x,
                                acc[mi][ni][h * 2 + 1] + bb.y);
            }
    }
}

// ---------------------------------------------------------------------------
extern "C" void kernel_launch(void* const* d_in, const int* in_sizes, int n_in,
                              void* d_out, int out_size)
{
    const float* xyz = (const float*)d_in[0];
    const float* Wq  = (const float*)d_in[1];
    const float* Wk  = (const float*)d_in[2];
    const float* Wv  = (const float*)d_in[3];
    const float* Wo  = (const float*)d_in[4];
    const float* bo  = (const float*)d_in[5];
    float* out = (float*)d_out;

    float* attn;
    if ((long long)out_size >= NPD_ + NHPP_) {
        attn = out + NPD_;
    } else {
        void* p = nullptr;
        cudaGetSymbolAddress(&p, g_attn);
        attn = (float*)p;
    }

    cudaFuncSetAttribute(scores_tc,  cudaFuncAttributeMaxDynamicSharedMemorySize, 55296);
    cudaFuncSetAttribute(pv_tc,      cudaFuncAttributeMaxDynamicSharedMemorySize, 182272);
    cudaFuncSetAttribute(outproj_tc, cudaFuncAttributeMaxDynamicSharedMemorySize, 73728);

    wo_split_kernel<<<(D_ * D_ + 255) / 256, 256>>>(Wo);
    qkv_kernel<<<dim3(P_ / 64, NH_), 256>>>(xyz, Wq, Wk, Wv);
    scores_tc<<<dim3(32, 16, NH_), 256, 55296>>>();
    pv_tc<<<dim3(16, NH_), 256, 182272>>>(attn);
    outproj_tc<<<dim3(4, 64), 256, 73728>>>(bo, out);
}

// round 14
// speedup vs baseline: 1.2627x; 1.1055x over previous
#include <cuda_runtime.h>
#include <cuda_bf16.h>
#include <cuda_fp16.h>
#include <stdint.h>
#include <math.h>

// Problem constants
constexpr int N_  = 4;
constexpr int P_  = 2048;
constexpr int D_  = 512;
constexpr int H_  = 8;
constexpr int HD_ = 64;
constexpr int NH_ = N_ * H_;                              // 32
constexpr long long NPD_  = (long long)N_ * P_ * D_;      // 4194304
constexpr long long NHPP_ = (long long)N_ * H_ * P_ * P_; // 134217728
constexpr float SCALE_ = 0.044194173824159216f;           // 1/sqrt(512)

// ---------------------------------------------------------------------------
// Scratch (device globals; allocation-free per harness rules)
// ---------------------------------------------------------------------------
__device__ __align__(16) __nv_bfloat16 g_qh[NH_ * P_ * HD_];
__device__ __align__(16) __nv_bfloat16 g_ql[NH_ * P_ * HD_];
__device__ __align__(16) __nv_bfloat16 g_kh[NH_ * P_ * HD_];
__device__ __align__(16) __nv_bfloat16 g_kl[NH_ * P_ * HD_];
__device__ __align__(16) __half        g_vth[NH_ * HD_ * P_]; // V^T fp16 hi
__device__ __align__(16) __half        g_vtl[NH_ * HD_ * P_]; // V^T fp16 lo
__device__ __align__(16) __half        g_u[NHPP_];   // u = exp(S - m_tile), fp16
__device__ __align__(16) __nv_bfloat16 g_oh[NPD_];   // O flat [n][p][512] hi
__device__ __align__(16) __nv_bfloat16 g_ol[NPD_];
__device__ __align__(16) __nv_bfloat16 g_woh[D_ * D_];
__device__ __align__(16) __nv_bfloat16 g_wol[D_ * D_];
__device__ float g_pm[NH_ * 32 * P_];     // per-64-ktile row max partial
__device__ float g_ps[NH_ * 32 * P_];     // per-64-ktile row sumexp partial
__device__ float g_attn[NHPP_];           // fallback if attention not in d_out

// ---------------------------------------------------------------------------
// Helpers
// ---------------------------------------------------------------------------
__device__ __forceinline__ uint32_t smem_u32(const void* p) {
    uint32_t a;
    asm("{ .reg .u64 t; cvta.to.shared.u64 t, %1; cvt.u32.u64 %0, t; }"
        : "=r"(a) : "l"(p));
    return a;
}

__device__ __forceinline__ void ldsm4(uint32_t* r, uint32_t a) {
    asm volatile("ldmatrix.sync.aligned.m8n8.x4.shared.b16 {%0,%1,%2,%3}, [%4];"
                 : "=r"(r[0]), "=r"(r[1]), "=r"(r[2]), "=r"(r[3]) : "r"(a));
}

// bf16 mma (scores / outproj)
__device__ __forceinline__ void mma16816(float* d, const uint32_t* a,
                                         uint32_t b0, uint32_t b1) {
    asm volatile("mma.sync.aligned.m16n8k16.row.col.f32.bf16.bf16.f32 "
                 "{%0,%1,%2,%3},{%4,%5,%6,%7},{%8,%9},{%0,%1,%2,%3};"
                 : "+f"(d[0]), "+f"(d[1]), "+f"(d[2]), "+f"(d[3])
                 : "r"(a[0]), "r"(a[1]), "r"(a[2]), "r"(a[3]), "r"(b0), "r"(b1));
}
// fp16 mma (pv)
__device__ __forceinline__ void mma16816h(float* d, const uint32_t* a,
                                          uint32_t b0, uint32_t b1) {
    asm volatile("mma.sync.aligned.m16n8k16.row.col.f32.f16.f16.f32 "
                 "{%0,%1,%2,%3},{%4,%5,%6,%7},{%8,%9},{%0,%1,%2,%3};"
                 : "+f"(d[0]), "+f"(d[1]), "+f"(d[2]), "+f"(d[3])
                 : "r"(a[0]), "r"(a[1]), "r"(a[2]), "r"(a[3]), "r"(b0), "r"(b1));
}

__device__ __forceinline__ void cpa16(uint32_t d, const void* s) {
    asm volatile("cp.async.cg.shared.global [%0], [%1], 16;" :: "r"(d), "l"(s));
}
#define CP_COMMIT() asm volatile("cp.async.commit_group;" ::: "memory")
#define CP_WAIT2()  asm volatile("cp.async.wait_group 2;" ::: "memory")
#define CP_WAIT1()  asm volatile("cp.async.wait_group 1;" ::: "memory")
#define CP_WAIT0()  asm volatile("cp.async.wait_group 0;" ::: "memory")

// Fast exp on the FFMA pipe (valid for x <= 0; ~1e-7 rel err). Avoids MUFU.
__device__ __forceinline__ float fexp(float x) {
    float t = x * 1.4426950408889634f;
    t = fmaxf(t, -120.f);
    float z = t + 12582912.f;
    int   n = __float_as_int(z) - 0x4B400000;
    float f = t - (z - 12582912.f);
    float r = 1.5403530393381609e-4f;
    r = fmaf(r, f, 1.3333558146428443e-3f);
    r = fmaf(r, f, 9.6181291076284772e-3f);
    r = fmaf(r, f, 5.5504108664821580e-2f);
    r = fmaf(r, f, 2.4022650695910072e-1f);
    r = fmaf(r, f, 6.9314718055994531e-1f);
    r = fmaf(r, f, 1.0f);
    return __int_as_float(__float_as_int(r) + (n << 23));
}

__device__ __forceinline__ unsigned short bfu(__nv_bfloat16 b) {
    return __bfloat16_as_ushort(b);
}

// ---------------------------------------------------------------------------
// K0: split Wo into bf16 hi/lo
// ---------------------------------------------------------------------------
__global__ __launch_bounds__(256) void wo_split_kernel(const float* __restrict__ Wo)
{
    int i = blockIdx.x * 256 + threadIdx.x;
    if (i < D_ * D_) {
        float v = Wo[i];
        __nv_bfloat16 hb = __float2bfloat16(v);
        g_woh[i] = hb;
        g_wol[i] = __float2bfloat16(v - __bfloat162float(hb));
    }
}

// ---------------------------------------------------------------------------
// K1: QKV projection (fp32 FFMA). Q/K -> bf16 hi/lo; V -> fp16 hi/lo, transposed.
// ---------------------------------------------------------------------------
__global__ __launch_bounds__(256) void qkv_kernel(
    const float* __restrict__ xyz,
    const float* __restrict__ Wq,
    const float* __restrict__ Wk,
    const float* __restrict__ Wv)
{
    __shared__ float xs[64][65];
    __shared__ float Wt[64][68];

    int ptile = blockIdx.x, nh = blockIdx.y;
    int n = nh / H_, h = nh % H_;
    int p0 = ptile * 64;
    int tid = threadIdx.x;

    for (int i = tid; i < 4096; i += 256) {
        int row = i >> 6, dd = i & 63;
        xs[row][dd] = xyz[(n * P_ + p0 + row) * D_ + h * HD_ + dd];
    }

    int tx = tid & 15, ty = tid >> 4;
    int r = ty * 4, c = tx * 4;
    const float* Ws[3] = {Wq, Wk, Wv};

    for (int m = 0; m < 3; ++m) {
        __syncthreads();
        const float* W = Ws[m];
        for (int i = tid; i < 4096; i += 256) {
            int e = i >> 6, dd = i & 63;
            Wt[dd][e] = W[i];
        }
        __syncthreads();

        float acc[4][4] = {};
        #pragma unroll
        for (int dd = 0; dd < 64; ++dd) {
            float a0 = xs[r + 0][dd], a1 = xs[r + 1][dd];
            float a2 = xs[r + 2][dd], a3 = xs[r + 3][dd];
            float4 b = *(const float4*)&Wt[dd][c];
            acc[0][0] += a0 * b.x; acc[0][1] += a0 * b.y; acc[0][2] += a0 * b.z; acc[0][3] += a0 * b.w;
            acc[1][0] += a1 * b.x; acc[1][1] += a1 * b.y; acc[1][2] += a1 * b.z; acc[1][3] += a1 * b.w;
            acc[2][0] += a2 * b.x; acc[2][1] += a2 * b.y; acc[2][2] += a2 * b.z; acc[2][3] += a2 * b.w;
            acc[3][0] += a3 * b.x; acc[3][1] += a3 * b.y; acc[3][2] += a3 * b.z; acc[3][3] += a3 * b.w;
        }

        if (m < 2) {
            float sc = (m == 0) ? SCALE_ : 1.0f;
            __nv_bfloat16* Ah = (m == 0) ? g_qh : g_kh;
            __nv_bfloat16* Al = (m == 0) ? g_ql : g_kl;
            #pragma unroll
            for (int i = 0; i < 4; ++i) {
                long long idx = ((long long)(nh * P_ + p0 + r + i)) * 64 + c;
                float v0 = acc[i][0] * sc, v1 = acc[i][1] * sc;
                float v2 = acc[i][2] * sc, v3 = acc[i][3] * sc;
                __nv_bfloat16 h0 = __float2bfloat16(v0), h1 = __float2bfloat16(v1);
                __nv_bfloat16 h2 = __float2bfloat16(v2), h3 = __float2bfloat16(v3);
                *(ushort4*)&Ah[idx] = make_ushort4(bfu(h0), bfu(h1), bfu(h2), bfu(h3));
                *(ushort4*)&Al[idx] = make_ushort4(
                    bfu(__float2bfloat16(v0 - __bfloat162float(h0))),
                    bfu(__float2bfloat16(v1 - __bfloat162float(h1))),
                    bfu(__float2bfloat16(v2 - __bfloat162float(h2))),
                    bfu(__float2bfloat16(v3 - __bfloat162float(h3))));
            }
        } else {
            __syncthreads();
            #pragma unroll
            for (int i = 0; i < 4; ++i)
                #pragma unroll
                for (int j = 0; j < 4; ++j)
                    xs[c + j][r + i] = acc[i][j];
            __syncthreads();
            for (int i = tid; i < 4096; i += 256) {
                int e = i >> 6, pp = i & 63;
                float v = xs[e][pp];
                __half hb = __float2half(v);
                long long idx = (long long)(nh * 64 + e) * P_ + p0 + pp;
                g_vth[idx] = hb;
                g_vtl[idx] = __float2half(v - __half2float(hb));
            }
        }
    }
}

// ---------------------------------------------------------------------------
// K2: S = QK^T via mma.sync bf16 hi/lo. CTA tile 128q x 64k, 256 thr, 8 warps,
//   warp tile 16x64 (wm = wid). In-warp stats; u stored as SINGLE fp16.
//   2 CTAs/SM via __launch_bounds__(256,2).
// smem (dynamic 55296, stride 144B): QH 0 / QL 18432 / KH 36864 / KL 46080.
//   Reused stage: u fp16 @0 (stride 144).
// ---------------------------------------------------------------------------
constexpr int TS6 = 144;

__global__ __launch_bounds__(256, 2) void scores_tc()
{
    extern __shared__ char sm[];
    uint32_t sb = smem_u32(sm);
    int tid = threadIdx.x, lane = tid & 31, wid = tid >> 5;
    int kt = blockIdx.x, qt = blockIdx.y, nh = blockIdx.z;
    int q0 = qt * 128, k0 = kt * 64;

    const int QH = 0, QL = 18432, KH = 36864, KL = 46080;
    {
        const __nv_bfloat16* qh = g_qh + (long long)(nh * P_ + q0) * 64;
        const __nv_bfloat16* ql = g_ql + (long long)(nh * P_ + q0) * 64;
        const __nv_bfloat16* kh = g_kh + (long long)(nh * P_ + k0) * 64;
        const __nv_bfloat16* kl = g_kl + (long long)(nh * P_ + k0) * 64;
        #pragma unroll
        for (int i = 0; i < 4; ++i) {
            int lin = i * 256 + tid;
            int row = lin >> 3, c8 = lin & 7;
            *(uint4*)(sm + QH + row * TS6 + c8 * 16) = *(const uint4*)(qh + row * 64 + c8 * 8);
            *(uint4*)(sm + QL + row * TS6 + c8 * 16) = *(const uint4*)(ql + row * 64 + c8 * 8);
        }
        #pragma unroll
        for (int i = 0; i < 2; ++i) {
            int lin = i * 256 + tid;
            int row = lin >> 3, c8 = lin & 7;
            *(uint4*)(sm + KH + row * TS6 + c8 * 16) = *(const uint4*)(kh + row * 64 + c8 * 8);
            *(uint4*)(sm + KL + row * TS6 + c8 * 16) = *(const uint4*)(kl + row * 64 + c8 * 8);
        }
    }
    __syncthreads();

    float acc[8][4] = {};
    uint32_t aoff = (uint32_t)(wid * 16 + (lane & 15)) * TS6 + ((lane & 16) ? 16u : 0u);
    uint32_t boff = (uint32_t)((lane & 7) + ((lane & 16) ? 8 : 0)) * TS6 +
                    ((lane & 8) ? 16u : 0u);

    #pragma unroll
    for (int pass = 0; pass < 3; ++pass) {
        uint32_t Ab = sb + (pass == 2 ? QL : QH);
        uint32_t Bb = sb + (pass == 1 ? KL : KH);
        #pragma unroll
        for (int ks = 0; ks < 4; ++ks) {
            uint32_t af[4], bf2[4][4];
            ldsm4(af, Ab + aoff + ks * 32);
            #pragma unroll
            for (int np = 0; np < 4; ++np)
                ldsm4(bf2[np], Bb + boff + np * 16 * TS6 + ks * 32);
            #pragma unroll
            for (int ni = 0; ni < 8; ++ni)
                mma16816(acc[ni], af,
                         bf2[ni >> 1][(ni & 1) * 2], bf2[ni >> 1][(ni & 1) * 2 + 1]);
        }
    }
    __syncthreads();   // operands dead; smem reused for u stage

    int g = lane >> 2, tg = lane & 3;
    long long sbase = (long long)(nh * 32 + kt) * P_ + q0;

    #pragma unroll
    for (int h = 0; h < 2; ++h) {
        int row = wid * 16 + h * 8 + g;
        float m = -1e30f;
        #pragma unroll
        for (int ni = 0; ni < 8; ++ni)
            m = fmaxf(m, fmaxf(acc[ni][h * 2], acc[ni][h * 2 + 1]));
        m = fmaxf(m, __shfl_xor_sync(0xFFFFFFFFu, m, 1));
        m = fmaxf(m, __shfl_xor_sync(0xFFFFFFFFu, m, 2));
        float s = 0.f;
        #pragma unroll
        for (int ni = 0; ni < 8; ++ni) {
            float u0 = fexp(acc[ni][h * 2] - m);
            float u1 = fexp(acc[ni][h * 2 + 1] - m);
            s += u0 + u1;
            int col = ni * 8 + tg * 2;
            __half2 hh = __floats2half2_rn(u0, u1);
            *(uint32_t*)(sm + row * TS6 + col * 2) =
                *reinterpret_cast<uint32_t*>(&hh);
        }
        s += __shfl_xor_sync(0xFFFFFFFFu, s, 1);
        s += __shfl_xor_sync(0xFFFFFFFFu, s, 2);
        if (tg == 0) {
            g_pm[sbase + row] = m;
            g_ps[sbase + row] = s;
        }
    }
    __syncthreads();

    long long ub = ((long long)nh << 22) + (long long)q0 * 2048 + k0;
    #pragma unroll
    for (int i = 0; i < 4; ++i) {
        int lin = i * 256 + tid;
        int row = lin >> 3, c8 = lin & 7;
        *(uint4*)(g_u + ub + (long long)row * 2048 + c8 * 8) =
            *(uint4*)(sm + row * TS6 + c8 * 16);
    }
}

// ---------------------------------------------------------------------------
// K3: pv. 256 thr, 8 fat warps (warp tile 16 rows x 64 cols).
//   32 k-tiles of 64; 4-stage cp.async pipeline, one sync per iteration.
//   fp16: u single, V hi/lo -> only 2 MMA passes.
// smem (dynamic 163840): stages s*36864: U+0 / VH+18432 / VL+27648
//   (stride 144). FACS @147456 (128 x 32 f32).
// ---------------------------------------------------------------------------
constexpr int PV_STG = 36864;
constexpr int PV_U = 0, PV_VH = 18432, PV_VL = 27648;
constexpr int PV_FACS = 147456;

__device__ __forceinline__ void pv_prefetch(
    uint32_t st, const __half* u,
    const __half* vh, const __half* vl, int k0, int tid)
{
    #pragma unroll
    for (int i = 0; i < 4; ++i) {
        int lin = i * 256 + tid;
        int row = lin >> 3, c8 = lin & 7;
        cpa16(st + PV_U + row * TS6 + c8 * 16, u + (long long)row * 2048 + k0 + c8 * 8);
    }
    #pragma unroll
    for (int i = 0; i < 2; ++i) {
        int lin = i * 256 + tid;
        int row = lin >> 3, c8 = lin & 7;
        cpa16(st + PV_VH + row * TS6 + c8 * 16, vh + (long long)row * P_ + k0 + c8 * 8);
        cpa16(st + PV_VL + row * TS6 + c8 * 16, vl + (long long)row * P_ + k0 + c8 * 8);
    }
    CP_COMMIT();
}

__global__ __launch_bounds__(256) void pv_tc(float* __restrict__ attn)
{
    extern __shared__ char sm[];
    uint32_t sb = smem_u32(sm);
    int tid = threadIdx.x, lane = tid & 31, wid = tid >> 5;
    int qt = blockIdx.x, nh = blockIdx.y;
    int q0 = qt * 128;

    const __half* vhp = g_vth + (long long)nh * 64 * P_;
    const __half* vlp = g_vtl + (long long)nh * 64 * P_;
    long long ub = ((long long)nh << 22) + (long long)q0 * 2048;
    const __half* up = g_u + ub;
    float* facs = (float*)(sm + PV_FACS);

    // prologue: prefetch tiles 0,1,2
    pv_prefetch(sb,              up, vhp, vlp, 0,   tid);
    pv_prefetch(sb + PV_STG,     up, vhp, vlp, 64,  tid);
    pv_prefetch(sb + 2 * PV_STG, up, vhp, vlp, 128, tid);

    // softmax combine factors (overlaps prefetch)
    if (tid < 128) {
        float pm[32];
        float M = -1e30f;
        #pragma unroll
        for (int t = 0; t < 32; ++t) {
            pm[t] = g_pm[(long long)(nh * 32 + t) * P_ + q0 + tid];
            M = fmaxf(M, pm[t]);
        }
        float L = 0.f;
        #pragma unroll
        for (int t = 0; t < 32; ++t) {
            float e = fexp(pm[t] - M);
            L += g_ps[(long long)(nh * 32 + t) * P_ + q0 + tid] * e;
            facs[tid * 32 + t] = e;
        }
        float inv = 1.f / L;
        #pragma unroll
        for (int t = 0; t < 32; ++t) facs[tid * 32 + t] *= inv;
    }

    float* S = attn + ub;
    float acc[8][4] = {};
    uint32_t aoff = (uint32_t)(wid * 16 + (lane & 15)) * TS6 + ((lane & 16) ? 16u : 0u);
    uint32_t boff = (uint32_t)((lane & 7) + ((lane & 16) ? 8 : 0)) * TS6 +
                    ((lane & 8) ? 16u : 0u);
    int g = lane >> 2;

    #pragma unroll 1
    for (int kb = 0; kb < 32; ++kb) {
        if (kb < 30)      { CP_WAIT2(); }
        else if (kb == 30){ CP_WAIT1(); }
        else              { CP_WAIT0(); }
        __syncthreads();   // tile kb ready; stage (kb+3)%4 free

        if (kb + 3 < 32)
            pv_prefetch(sb + ((kb + 3) & 3) * PV_STG, up, vhp, vlp,
                        (kb + 3) * 64, tid);

        uint32_t st = sb + (kb & 3) * PV_STG;
        char*    stc = sm + (kb & 3) * PV_STG;

        // acc_t = U_tile @ V_tile (2 fp16 passes: vh then vl), rescale-accum
        float acc_t[8][4] = {};
        #pragma unroll
        for (int pass = 0; pass < 2; ++pass) {
            uint32_t Ab = st + PV_U;
            uint32_t Bb = st + (pass ? PV_VL : PV_VH);
            #pragma unroll
            for (int ks = 0; ks < 4; ++ks) {
                uint32_t af[4], bf2[4][4];
                ldsm4(af, Ab + aoff + ks * 32);
                #pragma unroll
                for (int np = 0; np < 4; ++np)
                    ldsm4(bf2[np], Bb + boff + np * 16 * TS6 + ks * 32);
                #pragma unroll
                for (int ni = 0; ni < 8; ++ni)
                    mma16816h(acc_t[ni], af,
                              bf2[ni >> 1][(ni & 1) * 2], bf2[ni >> 1][(ni & 1) * 2 + 1]);
            }
        }
        float c0 = facs[(wid * 16 + g) * 32 + kb];
        float c1 = facs[(wid * 16 + 8 + g) * 32 + kb];
        #pragma unroll
        for (int ni = 0; ni < 8; ++ni) {
            acc[ni][0] = fmaf(c0, acc_t[ni][0], acc[ni][0]);
            acc[ni][1] = fmaf(c0, acc_t[ni][1], acc[ni][1]);
            acc[ni][2] = fmaf(c1, acc_t[ni][2], acc[ni][2]);
            acc[ni][3] = fmaf(c1, acc_t[ni][3], acc[ni][3]);
        }

        // probs output: p = u * fac (8 fp16 -> 8 fp32 per thread-iter)
        int k0 = kb * 64;
        #pragma unroll
        for (int i = 0; i < 4; ++i) {
            int lin = i * 256 + tid;
            int row = lin >> 3, c8 = lin & 7;
            uint4 w = *(uint4*)(stc + PV_U + row * TS6 + c8 * 16);
            float fac = facs[row * 32 + kb];
            float2 f0 = __half22float2(*reinterpret_cast<__half2*>(&w.x));
            float2 f1 = __half22float2(*reinterpret_cast<__half2*>(&w.y));
            float2 f2 = __half22float2(*reinterpret_cast<__half2*>(&w.z));
            float2 f3 = __half22float2(*reinterpret_cast<__half2*>(&w.w));
            long long base = (long long)row * 2048 + k0 + c8 * 8;
            *(float4*)&S[base] =
                make_float4(f0.x * fac, f0.y * fac, f1.x * fac, f1.y * fac);
            *(float4*)&S[base + 4] =
                make_float4(f2.x * fac, f2.y * fac, f3.x * fac, f3.y * fac);
        }
    }

    // Epilogue: stage O fp32 in smem, bf16 hi/lo to g_oh/g_ol
    int tg = lane & 3;
    float* Ost = (float*)sm;  // stride 68 floats
    __syncthreads();
    #pragma unroll
    for (int h = 0; h < 2; ++h) {
        int row = wid * 16 + h * 8 + g;
        #pragma unroll
        for (int ni = 0; ni < 8; ++ni)
            *(float2*)&Ost[row * 68 + ni * 8 + tg * 2] =
                make_float2(acc[ni][h * 2], acc[ni][h * 2 + 1]);
    }
    __syncthreads();
    int n = nh >> 3, h = nh & 7;
    #pragma unroll
    for (int i = 0; i < 4; ++i) {
        int lin = i * 256 + tid;
        int row = lin >> 3, c8 = lin & 7;
        long long dst = ((long long)(n * P_ + q0 + row)) * 512 + h * 64 + c8 * 8;
        const float* src = &Ost[row * 68 + c8 * 8];
        float v0 = src[0], v1 = src[1], v2 = src[2], v3 = src[3];
        float v4 = src[4], v5 = src[5], v6 = src[6], v7 = src[7];
        __nv_bfloat16 b0 = __float2bfloat16(v0), b1 = __float2bfloat16(v1);
        __nv_bfloat16 b2 = __float2bfloat16(v2), b3 = __float2bfloat16(v3);
        __nv_bfloat16 b4 = __float2bfloat16(v4), b5 = __float2bfloat16(v5);
        __nv_bfloat16 b6 = __float2bfloat16(v6), b7 = __float2bfloat16(v7);
        *(ushort4*)&g_oh[dst]     = make_ushort4(bfu(b0), bfu(b1), bfu(b2), bfu(b3));
        *(ushort4*)&g_oh[dst + 4] = make_ushort4(bfu(b4), bfu(b5), bfu(b6), bfu(b7));
        *(ushort4*)&g_ol[dst] = make_ushort4(
            bfu(__float2bfloat16(v0 - __bfloat162float(b0))),
            bfu(__float2bfloat16(v1 - __bfloat162float(b1))),
            bfu(__float2bfloat16(v2 - __bfloat162float(b2))),
            bfu(__float2bfloat16(v3 - __bfloat162float(b3))));
        *(ushort4*)&g_ol[dst + 4] = make_ushort4(
            bfu(__float2bfloat16(v4 - __bfloat162float(b4))),
            bfu(__float2bfloat16(v5 - __bfloat162float(b5))),
            bfu(__float2bfloat16(v6 - __bfloat162float(b6))),
            bfu(__float2bfloat16(v7 - __bfloat162float(b7))));
    }
}

// ---------------------------------------------------------------------------
// K4: out = O_flat @ Wo^T + bo via mma.sync bf16 hi/lo. 256 threads.
// Tile 128 x 128, k-chunks of 64; warp tile 32 x 64 (wm = wid>>1, wn = wid&1).
// smem (dynamic 73728): AH 0 / AL 18432 / BH 36864 / BL 55296 (stride 144B).
// ---------------------------------------------------------------------------
__global__ __launch_bounds__(256) void outproj_tc(
    const float* __restrict__ bo,
    float* __restrict__ out)
{
    extern __shared__ char sm[];
    uint32_t sb = smem_u32(sm);
    int tid = threadIdx.x, lane = tid & 31, wid = tid >> 5;
    int ct = blockIdx.x, rt = blockIdx.y;
    int r0 = rt * 128, c0 = ct * 128;

    const int AH = 0, AL = 18432, BH = 36864, BL = 55296;
    int wm = wid >> 1, wn = wid & 1;
    float acc[2][8][4] = {};
    uint32_t aoff = (uint32_t)(wm * 32 + (lane & 15)) * TS6 + ((lane & 16) ? 16u : 0u);
    uint32_t boff = (uint32_t)(wn * 64 + (lane & 7) + ((lane & 16) ? 8 : 0)) * TS6 +
                    ((lane & 8) ? 16u : 0u);

    #pragma unroll 1
    for (int kb = 0; kb < 8; ++kb) {
        int k0 = kb * 64;
        #pragma unroll
        for (int i = 0; i < 4; ++i) {
            int lin = i * 256 + tid;
            int row = lin >> 3, c8 = lin & 7;
            long long asrc = (long long)(r0 + row) * 512 + k0 + c8 * 8;
            long long bsrc = (long long)(c0 + row) * 512 + k0 + c8 * 8;
            *(uint4*)(sm + AH + row * TS6 + c8 * 16) = *(const uint4*)(g_oh + asrc);
            *(uint4*)(sm + AL + row * TS6 + c8 * 16) = *(const uint4*)(g_ol + asrc);
            *(uint4*)(sm + BH + row * TS6 + c8 * 16) = *(const uint4*)(g_woh + bsrc);
            *(uint4*)(sm + BL + row * TS6 + c8 * 16) = *(const uint4*)(g_wol + bsrc);
        }
        __syncthreads();

        #pragma unroll
        for (int pass = 0; pass < 3; ++pass) {
            uint32_t Ab = sb + (pass == 2 ? AL : AH);
            uint32_t Bb = sb + (pass == 1 ? BL : BH);
            #pragma unroll
            for (int ks = 0; ks < 4; ++ks) {
                uint32_t af[2][4], bf2[4][4];
                ldsm4(af[0], Ab + aoff + ks * 32);
                ldsm4(af[1], Ab + aoff + 16 * TS6 + ks * 32);
                #pragma unroll
                for (int np = 0; np < 4; ++np)
                    ldsm4(bf2[np], Bb + boff + np * 16 * TS6 + ks * 32);
                #pragma unroll
                for (int mi = 0; mi < 2; ++mi)
                    #pragma unroll
                    for (int ni = 0; ni < 8; ++ni)
                        mma16816(acc[mi][ni], af[mi],
                                 bf2[ni >> 1][(ni & 1) * 2], bf2[ni >> 1][(ni & 1) * 2 + 1]);
            }
        }
        __syncthreads();
    }

    int g = lane >> 2, tg = lane & 3;
    #pragma unroll
    for (int ni = 0; ni < 8; ++ni) {
        int col = wn * 64 + ni * 8 + tg * 2;
        float2 bb = *(const float2*)&bo[c0 + col];
        #pragma unroll
        for (int mi = 0; mi < 2; ++mi)
            #pragma unroll
            for (int h = 0; h < 2; ++h) {
                int row = wm * 32 + mi * 16 + h * 8 + g;
                *(float2*)&out[(long long)(r0 + row) * 512 + c0 + col] =
                    make_float2(acc[mi][ni][h * 2] + bb.x,
                                acc[mi][ni][h * 2 + 1] + bb.y);
            }
    }
}

// ---------------------------------------------------------------------------
extern "C" void kernel_launch(void* const* d_in, const int* in_sizes, int n_in,
                              void* d_out, int out_size)
{
    const float* xyz = (const float*)d_in[0];
    const float* Wq  = (const float*)d_in[1];
    const float* Wk  = (const float*)d_in[2];
    const float* Wv  = (const float*)d_in[3];
    const float* Wo  = (const float*)d_in[4];
    const float* bo  = (const float*)d_in[5];
    float* out = (float*)d_out;

    float* attn;
    if ((long long)out_size >= NPD_ + NHPP_) {
        attn = out + NPD_;
    } else {
        void* p = nullptr;
        cudaGetSymbolAddress(&p, g_attn);
        attn = (float*)p;
    }

    cudaFuncSetAttribute(scores_tc,  cudaFuncAttributeMaxDynamicSharedMemorySize, 55296);
    cudaFuncSetAttribute(pv_tc,      cudaFuncAttributeMaxDynamicSharedMemorySize, 163840);
    cudaFuncSetAttribute(outproj_tc, cudaFuncAttributeMaxDynamicSharedMemorySize, 73728);

    wo_split_kernel<<<(D_ * D_ + 255) / 256, 256>>>(Wo);
    qkv_kernel<<<dim3(P_ / 64, NH_), 256>>>(xyz, Wq, Wk, Wv);
    scores_tc<<<dim3(32, 16, NH_), 256, 55296>>>();
    pv_tc<<<dim3(16, NH_), 256, 163840>>>(attn);
    outproj_tc<<<dim3(4, 64), 256, 73728>>>(bo, out);
}